// round 15
// baseline (speedup 1.0000x reference)
#include <cuda_runtime.h>
#include <cuda_fp16.h>
#include <math.h>

#define NN 50000
#define EE 800000
#define HID 16
#define HEADS 8
#define F1 128   /* HEADS*HID */
#define CLS 40
#define SCAN_B 512
#define NSB ((NN + SCAN_B - 1) / SCAN_B)   /* 98 */

// ---------------- scratch ----------------------------------------------------
__device__ __align__(16) float g_feat1[NN * F1];
__device__ float g_el1[NN * HEADS];
__device__ float g_er1[NN * HEADS];
__device__ __align__(16) float g_h[NN * F1];
__device__ __align__(16) float g_feat2[NN * CLS];
__device__ float g_el2[NN];
__device__ float g_er2[NN];
__device__ int   g_deg[NN];        // zero-initialized; scanAB re-zeroes each run
__device__ int   g_off[NN];
__device__ int   g_bsum[NSB];
__device__ int   g_bofs[NSB];
__device__ int   g_rank[EE];
__device__ int   g_csrc[EE];
__device__ unsigned long long g_ctr = 0;   // monotonic (never reset)

__device__ __forceinline__ int off_at(int i) {
    return (i == NN) ? EE : (g_off[i] + g_bofs[i >> 9]);
}

// ---------------- CSR build --------------------------------------------------
__global__ void k_count(const int* __restrict__ dst) {
    int t = blockIdx.x * blockDim.x + threadIdx.x;
    if (t >= EE / 2) return;
    int2 d = ((const int2*)dst)[t];
    int2 r;
    r.x = atomicAdd(&g_deg[d.x], 1);
    r.y = atomicAdd(&g_deg[d.y], 1);
    ((int2*)g_rank)[t] = r;
}

__global__ void __launch_bounds__(SCAN_B) k_scanAB() {
    __shared__ int wsum[16];
    __shared__ int slast;
    int tid = threadIdx.x, lane = tid & 31, wid = tid >> 5;
    int i = blockIdx.x * SCAN_B + tid;
    int v = (i < NN) ? g_deg[i] : 0;
    if (i < NN) g_deg[i] = 0;       // self-clean for next graph replay
    int x = v;
    #pragma unroll
    for (int o = 1; o < 32; o <<= 1) {
        int y = __shfl_up_sync(0xffffffffu, x, o);
        if (lane >= o) x += y;
    }
    if (lane == 31) wsum[wid] = x;
    __syncthreads();
    if (wid == 0 && lane < 16) {
        int y = wsum[lane];
        #pragma unroll
        for (int o = 1; o < 16; o <<= 1) {
            int z = __shfl_up_sync(0x0000ffffu, y, o);
            if (lane >= o) y += z;
        }
        wsum[lane] = y;
    }
    __syncthreads();
    int wofs = wid ? wsum[wid - 1] : 0;
    if (i < NN) g_off[i] = wofs + x - v;
    if (tid == SCAN_B - 1) g_bsum[blockIdx.x] = wofs + x;

    __threadfence();
    if (tid == 0) {
        unsigned long long c = atomicAdd(&g_ctr, 1ULL);
        slast = ((c % (unsigned long long)NSB) == (unsigned long long)(NSB - 1));
    }
    __syncthreads();
    if (slast && tid < 32) {
        volatile int* bs = g_bsum;
        int carry = 0;
        #pragma unroll
        for (int c = 0; c < (NSB + 31) / 32; c++) {
            int j = c * 32 + tid;
            int vv = (j < NSB) ? bs[j] : 0;
            int xx = vv;
            #pragma unroll
            for (int o = 1; o < 32; o <<= 1) {
                int y = __shfl_up_sync(0xffffffffu, xx, o);
                if (tid >= o) xx += y;
            }
            if (j < NSB) g_bofs[j] = carry + xx - vv;
            carry += __shfl_sync(0xffffffffu, xx, 31);
        }
    }
}

__global__ void k_scatter(const int* __restrict__ src, const int* __restrict__ dst) {
    int t = blockIdx.x * blockDim.x + threadIdx.x;
    if (t >= EE / 2) return;
    int2 d = ((const int2*)dst)[t];
    int2 s = ((const int2*)src)[t];
    int2 r = ((const int2*)g_rank)[t];
    g_csrc[g_off[d.x] + g_bofs[d.x >> 9] + r.x] = s.x;
    g_csrc[g_off[d.y] + g_bofs[d.y >> 9] + r.y] = s.y;
}

// ---------------- GEMM1 via tensor cores (mma.sync m16n8k16, f16 in, f32 acc) -
// 64 rows x 128 cols per block, 4 warps (16 rows each), K=128 resident in smem.
__global__ void __launch_bounds__(128) k_gemm1(const float* __restrict__ X,
                                               const float* __restrict__ W,
                                               const float* __restrict__ al,
                                               const float* __restrict__ ar) {
    __shared__ __half Xs[64][136];    // row stride 272B (16B-aligned, cf-free)
    __shared__ __half Ws[128][136];
    int tid = threadIdx.x;
    int lane = tid & 31, w = tid >> 5;
    int row0 = blockIdx.x * 64;

    // load X tile (fp32 -> fp16): 64 rows x 32 float4
    for (int i = tid; i < 2048; i += 128) {
        int r = i >> 5, c4 = (i & 31) * 4;
        int gr = row0 + r;
        float4 v = (gr < NN) ? *(const float4*)&X[gr * 128 + c4]
                             : make_float4(0.f, 0.f, 0.f, 0.f);
        *(__half2*)&Xs[r][c4]     = __floats2half2_rn(v.x, v.y);
        *(__half2*)&Xs[r][c4 + 2] = __floats2half2_rn(v.z, v.w);
    }
    // load W (fp32 -> fp16): 128 rows x 32 float4
    for (int i = tid; i < 4096; i += 128) {
        int r = i >> 5, c4 = (i & 31) * 4;
        float4 v = *(const float4*)&W[r * 128 + c4];
        *(__half2*)&Ws[r][c4]     = __floats2half2_rn(v.x, v.y);
        *(__half2*)&Ws[r][c4 + 2] = __floats2half2_rn(v.z, v.w);
    }
    __syncthreads();

    float c[16][4];
    #pragma unroll
    for (int n = 0; n < 16; n++)
        #pragma unroll
        for (int j = 0; j < 4; j++) c[n][j] = 0.f;

    // ldmatrix lane addressing (same row/col-half formula for A and B)
    int mrow = (lane & 7) + ((lane >> 3) & 1) * 8;
    int mcol = (lane >> 4) * 8;
    unsigned xa = (unsigned)__cvta_generic_to_shared(&Xs[w * 16 + mrow][mcol]);
    unsigned wa = (unsigned)__cvta_generic_to_shared(&Ws[mrow][mcol]);

    #pragma unroll
    for (int ks = 0; ks < 8; ks++) {
        unsigned a0, a1, a2, a3;
        asm volatile("ldmatrix.sync.aligned.m8n8.x4.shared.b16 {%0,%1,%2,%3}, [%4];"
                     : "=r"(a0), "=r"(a1), "=r"(a2), "=r"(a3)
                     : "r"(xa + ks * 32));
        #pragma unroll
        for (int nt2 = 0; nt2 < 8; nt2++) {
            unsigned b0, b1, b2, b3;
            asm volatile("ldmatrix.sync.aligned.m8n8.x4.trans.shared.b16 {%0,%1,%2,%3}, [%4];"
                         : "=r"(b0), "=r"(b1), "=r"(b2), "=r"(b3)
                         : "r"(wa + ks * (16 * 272) + nt2 * 32));
            asm volatile("mma.sync.aligned.m16n8k16.row.col.f32.f16.f16.f32 "
                         "{%0,%1,%2,%3}, {%4,%5,%6,%7}, {%8,%9}, {%0,%1,%2,%3};"
                         : "+f"(c[nt2 * 2][0]), "+f"(c[nt2 * 2][1]),
                           "+f"(c[nt2 * 2][2]), "+f"(c[nt2 * 2][3])
                         : "r"(a0), "r"(a1), "r"(a2), "r"(a3), "r"(b0), "r"(b1));
            asm volatile("mma.sync.aligned.m16n8k16.row.col.f32.f16.f16.f32 "
                         "{%0,%1,%2,%3}, {%4,%5,%6,%7}, {%8,%9}, {%0,%1,%2,%3};"
                         : "+f"(c[nt2 * 2 + 1][0]), "+f"(c[nt2 * 2 + 1][1]),
                           "+f"(c[nt2 * 2 + 1][2]), "+f"(c[nt2 * 2 + 1][3])
                         : "r"(a0), "r"(a1), "r"(a2), "r"(a3), "r"(b2), "r"(b3));
        }
    }

    // c-frag layout: lane holds rows r0=(lane>>2), r1=r0+8 (within warp tile),
    // cols nt*8 + (lane&3)*2 + {0,1}
    int r0 = w * 16 + (lane >> 2);
    int r1 = r0 + 8;
    int cbase = (lane & 3) * 2;
    int gr0 = row0 + r0, gr1 = row0 + r1;

    #pragma unroll
    for (int nt = 0; nt < 16; nt++) {
        int col = nt * 8 + cbase;
        if (gr0 < NN)
            *(float2*)&g_feat1[gr0 * 128 + col] = make_float2(c[nt][0], c[nt][1]);
        if (gr1 < NN)
            *(float2*)&g_feat1[gr1 * 128 + col] = make_float2(c[nt][2], c[nt][3]);
    }

    // fused el/er: head h covers cols h*16..h*16+15 = n-tiles 2h, 2h+1.
    // lane owns 4 dims of the head; reduce over the quad (shfl_xor 1,2).
    #pragma unroll
    for (int h = 0; h < 8; h++) {
        float2 ala = *(const float2*)&al[h * 16 + cbase];
        float2 alb = *(const float2*)&al[h * 16 + 8 + cbase];
        float2 ara = *(const float2*)&ar[h * 16 + cbase];
        float2 arb = *(const float2*)&ar[h * 16 + 8 + cbase];
        const float* ca = c[2 * h];
        const float* cb = c[2 * h + 1];
        float el0 = ca[0] * ala.x + ca[1] * ala.y + cb[0] * alb.x + cb[1] * alb.y;
        float er0 = ca[0] * ara.x + ca[1] * ara.y + cb[0] * arb.x + cb[1] * arb.y;
        float el1 = ca[2] * ala.x + ca[3] * ala.y + cb[2] * alb.x + cb[3] * alb.y;
        float er1 = ca[2] * ara.x + ca[3] * ara.y + cb[2] * arb.x + cb[3] * arb.y;
        el0 += __shfl_xor_sync(0xffffffffu, el0, 1);
        el0 += __shfl_xor_sync(0xffffffffu, el0, 2);
        er0 += __shfl_xor_sync(0xffffffffu, er0, 1);
        er0 += __shfl_xor_sync(0xffffffffu, er0, 2);
        el1 += __shfl_xor_sync(0xffffffffu, el1, 1);
        el1 += __shfl_xor_sync(0xffffffffu, el1, 2);
        er1 += __shfl_xor_sync(0xffffffffu, er1, 1);
        er1 += __shfl_xor_sync(0xffffffffu, er1, 2);
        if ((lane & 3) == 0) {
            if (gr0 < NN) { g_el1[gr0 * 8 + h] = el0; g_er1[gr0 * 8 + h] = er0; }
            if (gr1 < NN) { g_el1[gr1 * 8 + h] = el1; g_er1[gr1 * 8 + h] = er1; }
        }
    }
}

// ---------------- layer1 fused softmax+aggregate (4-edge unroll, fp32) -------
__global__ void __launch_bounds__(256) k_node1(const float* __restrict__ b1) {
    int v = (blockIdx.x * blockDim.x + threadIdx.x) >> 5;
    if (v >= NN) return;
    int lane = threadIdx.x & 31;
    int h4 = lane >> 2;
    int beg = off_at(v), end = off_at(v + 1);
    float erh = g_er1[v * 8 + h4];

    float denom = 0.f;
    float4 acc = make_float4(0.f, 0.f, 0.f, 0.f);

    auto edge = [&](int s) {
        float e0 = g_el1[s * 8 + h4] + erh;
        float e = fmaxf(e0, 0.2f * e0);
        float w = __expf(e);
        float4 f = *(const float4*)&g_feat1[s * 128 + lane * 4];
        denom += w;
        acc.x += w * f.x; acc.y += w * f.y;
        acc.z += w * f.z; acc.w += w * f.w;
    };

    int p = beg;
    while ((p & 3) && p < end) { edge(g_csrc[p]); p++; }
    for (; p + 4 <= end; p += 4) {
        int4 ss = *(const int4*)&g_csrc[p];
        edge(ss.x); edge(ss.y); edge(ss.z); edge(ss.w);
    }
    for (; p < end; p++) edge(g_csrc[p]);

    float inv = 1.f / (denom + 1e-9f);
    float4 b = *(const float4*)&b1[lane * 4];
    float4 r;
    r.x = acc.x * inv + b.x; r.y = acc.y * inv + b.y;
    r.z = acc.z * inv + b.z; r.w = acc.w * inv + b.w;
    r.x = (r.x > 0.f) ? r.x : (__expf(r.x) - 1.f);
    r.y = (r.y > 0.f) ? r.y : (__expf(r.y) - 1.f);
    r.z = (r.z > 0.f) ? r.z : (__expf(r.z) - 1.f);
    r.w = (r.w > 0.f) ? r.w : (__expf(r.w) - 1.f);
    *(float4*)&g_h[v * 128 + lane * 4] = r;
}

// ---------------- GEMM2 + fused coef2 epilogue (fp32) ------------------------
__global__ void __launch_bounds__(240) k_gemm2(const float* __restrict__ W,
                                               const float* __restrict__ al,
                                               const float* __restrict__ ar) {
    __shared__ __align__(16) float Xs[48][129];
    __shared__ __align__(16) float Ws[128][40];
    __shared__ float pelA[240], perA[240], pelB[240], perB[240];
    int tid = threadIdx.x;
    int tc = tid % 10, rl = tid / 10;
    int row0 = blockIdx.x * 48;
    for (int i = tid; i < 48 * 128; i += 240) {
        int r = i >> 7, c = i & 127;
        int gr = row0 + r;
        Xs[r][c] = (gr < NN) ? g_h[gr * 128 + c] : 0.f;
    }
    for (int i = tid; i < 128 * 40; i += 240)
        Ws[i / 40][i % 40] = W[i];
    __syncthreads();

    float a0[4] = {0, 0, 0, 0}, a1[4] = {0, 0, 0, 0};
    #pragma unroll 4
    for (int k = 0; k < 128; k++) {
        float4 w = *(const float4*)&Ws[k][tc * 4];
        float xa = Xs[rl][k];
        float xb = Xs[rl + 24][k];
        a0[0] += xa * w.x; a0[1] += xa * w.y; a0[2] += xa * w.z; a0[3] += xa * w.w;
        a1[0] += xb * w.x; a1[1] += xb * w.y; a1[2] += xb * w.z; a1[3] += xb * w.w;
    }
    int ra = row0 + rl, rb = ra + 24;
    if (ra < NN)
        *(float4*)&g_feat2[ra * 40 + tc * 4] = make_float4(a0[0], a0[1], a0[2], a0[3]);
    if (rb < NN)
        *(float4*)&g_feat2[rb * 40 + tc * 4] = make_float4(a1[0], a1[1], a1[2], a1[3]);

    float4 av = *(const float4*)&al[tc * 4];
    float4 rv = *(const float4*)&ar[tc * 4];
    pelA[tid] = a0[0] * av.x + a0[1] * av.y + a0[2] * av.z + a0[3] * av.w;
    perA[tid] = a0[0] * rv.x + a0[1] * rv.y + a0[2] * rv.z + a0[3] * rv.w;
    pelB[tid] = a1[0] * av.x + a1[1] * av.y + a1[2] * av.z + a1[3] * av.w;
    perB[tid] = a1[0] * rv.x + a1[1] * rv.y + a1[2] * rv.z + a1[3] * rv.w;
    __syncthreads();
    if (tid < 48) {
        int r = (tid < 24) ? tid : (tid - 24);
        const float* pe = (tid < 24) ? pelA : pelB;
        const float* pr = (tid < 24) ? perA : perB;
        float el = 0.f, er = 0.f;
        #pragma unroll
        for (int j = 0; j < 10; j++) {
            el += pe[r * 10 + j];
            er += pr[r * 10 + j];
        }
        int gr = (tid < 24) ? (row0 + r) : (row0 + 24 + r);
        if (gr < NN) { g_el2[gr] = el; g_er2[gr] = er; }
    }
}

// ---------------- layer2 fused softmax+aggregate (4-edge unroll, fp32) -------
__global__ void __launch_bounds__(256) k_node2(const float* __restrict__ b2,
                                               float* __restrict__ out) {
    int v = (blockIdx.x * blockDim.x + threadIdx.x) >> 5;
    if (v >= NN) return;
    int lane = threadIdx.x & 31;
    int beg = off_at(v), end = off_at(v + 1);
    float erv = g_er2[v];
    bool act = lane < 20;

    float denom = 0.f;
    float2 acc = make_float2(0.f, 0.f);

    auto edge = [&](int s) {
        float e0 = g_el2[s] + erv;
        float e = fmaxf(e0, 0.2f * e0);
        float w = __expf(e);
        denom += w;
        if (act) {
            float2 f = *(const float2*)&g_feat2[s * 40 + lane * 2];
            acc.x += w * f.x;
            acc.y += w * f.y;
        }
    };

    int p = beg;
    while ((p & 3) && p < end) { edge(g_csrc[p]); p++; }
    for (; p + 4 <= end; p += 4) {
        int4 ss = *(const int4*)&g_csrc[p];
        edge(ss.x); edge(ss.y); edge(ss.z); edge(ss.w);
    }
    for (; p < end; p++) edge(g_csrc[p]);

    float inv = 1.f / (denom + 1e-9f);
    if (act) {
        float2 r;
        r.x = acc.x * inv + b2[lane * 2];
        r.y = acc.y * inv + b2[lane * 2 + 1];
        *(float2*)&out[v * 40 + lane * 2] = r;
    }
}

// ---------------- streams/events (created once, before main) ------------------
static cudaStream_t g_s2;
static cudaEvent_t g_evFork, g_evJoin;
static struct StreamInit {
    StreamInit() {
        cudaStreamCreate(&g_s2);
        cudaEventCreateWithFlags(&g_evFork, cudaEventDisableTiming);
        cudaEventCreateWithFlags(&g_evJoin, cudaEventDisableTiming);
    }
} g_stream_init;

// ---------------- launch ------------------------------------------------------
extern "C" void kernel_launch(void* const* d_in, const int* in_sizes, int n_in,
                              void* d_out, int out_size) {
    const float* features = (const float*)d_in[0];
    const int*   esrc     = (const int*)d_in[1];
    const int*   edst     = (const int*)d_in[2];
    const float* W1       = (const float*)d_in[3];
    const float* al1      = (const float*)d_in[4];
    const float* ar1      = (const float*)d_in[5];
    const float* b1       = (const float*)d_in[6];
    const float* W2       = (const float*)d_in[7];
    const float* al2      = (const float*)d_in[8];
    const float* ar2      = (const float*)d_in[9];
    const float* b2       = (const float*)d_in[10];
    float* out = (float*)d_out;

    // CSR chain first (main stream); gemm1 forked on s2 at launch idx 3
    cudaEventRecord(g_evFork, 0);
    cudaStreamWaitEvent(g_s2, g_evFork, 0);
    k_count<<<(EE / 2 + 255) / 256, 256>>>(edst);                      // 0
    k_scanAB<<<NSB, SCAN_B>>>();                                       // 1
    k_scatter<<<(EE / 2 + 255) / 256, 256>>>(esrc, edst);              // 2
    k_gemm1<<<(NN + 63) / 64, 128, 0, g_s2>>>(features, W1, al1, ar1); // 3 (profiled)
    cudaEventRecord(g_evJoin, g_s2);
    cudaStreamWaitEvent(0, g_evJoin, 0);

    k_node1<<<(NN * 32 + 255) / 256, 256>>>(b1);                       // 4
    k_gemm2<<<(NN + 47) / 48, 240>>>(W2, al2, ar2);                    // 5
    k_node2<<<(NN * 32 + 255) / 256, 256>>>(b2, out);                  // 6
}

// round 16
// speedup vs baseline: 1.4501x; 1.4501x over previous
#include <cuda_runtime.h>
#include <cuda_fp16.h>
#include <math.h>

#define NN 50000
#define EE 800000
#define HID 16
#define HEADS 8
#define F1 128   /* HEADS*HID */
#define CLS 40
#define SCAN_B 512
#define NSB ((NN + SCAN_B - 1) / SCAN_B)   /* 98 */

// ---------------- scratch ----------------------------------------------------
__device__ __align__(16) float g_feat1[NN * F1];
__device__ float g_el1[NN * HEADS];
__device__ float g_er1[NN * HEADS];
__device__ __align__(16) float g_h[NN * F1];
__device__ __align__(16) float g_feat2[NN * CLS];
__device__ float g_el2[NN];
__device__ float g_er2[NN];
__device__ int   g_deg[NN];        // zero-initialized; scanAB re-zeroes each run
__device__ int   g_off[NN];
__device__ int   g_bsum[NSB];
__device__ int   g_bofs[NSB];
__device__ int   g_rank[EE];
__device__ int   g_csrc[EE];
__device__ unsigned long long g_ctr = 0;   // monotonic (never reset)

__device__ __forceinline__ int off_at(int i) {
    return (i == NN) ? EE : (g_off[i] + g_bofs[i >> 9]);
}

// ---------------- CSR build --------------------------------------------------
__global__ void k_count(const int* __restrict__ dst) {
    int t = blockIdx.x * blockDim.x + threadIdx.x;
    if (t >= EE / 2) return;
    int2 d = ((const int2*)dst)[t];
    int2 r;
    r.x = atomicAdd(&g_deg[d.x], 1);
    r.y = atomicAdd(&g_deg[d.y], 1);
    ((int2*)g_rank)[t] = r;
}

__global__ void __launch_bounds__(SCAN_B) k_scanAB() {
    __shared__ int wsum[16];
    __shared__ int slast;
    int tid = threadIdx.x, lane = tid & 31, wid = tid >> 5;
    int i = blockIdx.x * SCAN_B + tid;
    int v = (i < NN) ? g_deg[i] : 0;
    if (i < NN) g_deg[i] = 0;       // self-clean for next graph replay
    int x = v;
    #pragma unroll
    for (int o = 1; o < 32; o <<= 1) {
        int y = __shfl_up_sync(0xffffffffu, x, o);
        if (lane >= o) x += y;
    }
    if (lane == 31) wsum[wid] = x;
    __syncthreads();
    if (wid == 0 && lane < 16) {
        int y = wsum[lane];
        #pragma unroll
        for (int o = 1; o < 16; o <<= 1) {
            int z = __shfl_up_sync(0x0000ffffu, y, o);
            if (lane >= o) y += z;
        }
        wsum[lane] = y;
    }
    __syncthreads();
    int wofs = wid ? wsum[wid - 1] : 0;
    if (i < NN) g_off[i] = wofs + x - v;
    if (tid == SCAN_B - 1) g_bsum[blockIdx.x] = wofs + x;

    __threadfence();
    if (tid == 0) {
        unsigned long long c = atomicAdd(&g_ctr, 1ULL);
        slast = ((c % (unsigned long long)NSB) == (unsigned long long)(NSB - 1));
    }
    __syncthreads();
    if (slast && tid < 32) {
        volatile int* bs = g_bsum;
        int carry = 0;
        #pragma unroll
        for (int c = 0; c < (NSB + 31) / 32; c++) {
            int j = c * 32 + tid;
            int vv = (j < NSB) ? bs[j] : 0;
            int xx = vv;
            #pragma unroll
            for (int o = 1; o < 32; o <<= 1) {
                int y = __shfl_up_sync(0xffffffffu, xx, o);
                if (tid >= o) xx += y;
            }
            if (j < NSB) g_bofs[j] = carry + xx - vv;
            carry += __shfl_sync(0xffffffffu, xx, 31);
        }
    }
}

__global__ void k_scatter(const int* __restrict__ src, const int* __restrict__ dst) {
    int t = blockIdx.x * blockDim.x + threadIdx.x;
    if (t >= EE / 2) return;
    int2 d = ((const int2*)dst)[t];
    int2 s = ((const int2*)src)[t];
    int2 r = ((const int2*)g_rank)[t];
    g_csrc[g_off[d.x] + g_bofs[d.x >> 9] + r.x] = s.x;
    g_csrc[g_off[d.y] + g_bofs[d.y >> 9] + r.y] = s.y;
}

// ---------------- GEMM1 via tensor cores (mma.sync m16n8k16) -----------------
// ILP fix: per k-step, batch all 8 B-fragment ldmatrix loads before the MMAs.
__global__ void __launch_bounds__(128) k_gemm1(const float* __restrict__ X,
                                               const float* __restrict__ W,
                                               const float* __restrict__ al,
                                               const float* __restrict__ ar) {
    __shared__ __half Xs[64][136];    // row stride 272B
    __shared__ __half Ws[128][136];
    int tid = threadIdx.x;
    int lane = tid & 31, w = tid >> 5;
    int row0 = blockIdx.x * 64;

    for (int i = tid; i < 2048; i += 128) {
        int r = i >> 5, c4 = (i & 31) * 4;
        int gr = row0 + r;
        float4 v = (gr < NN) ? *(const float4*)&X[gr * 128 + c4]
                             : make_float4(0.f, 0.f, 0.f, 0.f);
        *(__half2*)&Xs[r][c4]     = __floats2half2_rn(v.x, v.y);
        *(__half2*)&Xs[r][c4 + 2] = __floats2half2_rn(v.z, v.w);
    }
    for (int i = tid; i < 4096; i += 128) {
        int r = i >> 5, c4 = (i & 31) * 4;
        float4 v = *(const float4*)&W[r * 128 + c4];
        *(__half2*)&Ws[r][c4]     = __floats2half2_rn(v.x, v.y);
        *(__half2*)&Ws[r][c4 + 2] = __floats2half2_rn(v.z, v.w);
    }
    __syncthreads();

    float c[16][4];
    #pragma unroll
    for (int n = 0; n < 16; n++)
        #pragma unroll
        for (int j = 0; j < 4; j++) c[n][j] = 0.f;

    int mrow = (lane & 7) + ((lane >> 3) & 1) * 8;
    int mcol = (lane >> 4) * 8;
    unsigned xa = (unsigned)__cvta_generic_to_shared(&Xs[w * 16 + mrow][mcol]);
    unsigned wa = (unsigned)__cvta_generic_to_shared(&Ws[mrow][mcol]);

    #pragma unroll
    for (int ks = 0; ks < 8; ks++) {
        unsigned a0, a1, a2, a3;
        asm volatile("ldmatrix.sync.aligned.m8n8.x4.shared.b16 {%0,%1,%2,%3}, [%4];"
                     : "=r"(a0), "=r"(a1), "=r"(a2), "=r"(a3)
                     : "r"(xa + ks * 32));
        unsigned b[8][4];
        #pragma unroll
        for (int nt2 = 0; nt2 < 8; nt2++) {
            asm volatile("ldmatrix.sync.aligned.m8n8.x4.trans.shared.b16 {%0,%1,%2,%3}, [%4];"
                         : "=r"(b[nt2][0]), "=r"(b[nt2][1]),
                           "=r"(b[nt2][2]), "=r"(b[nt2][3])
                         : "r"(wa + ks * (16 * 272) + nt2 * 32));
        }
        #pragma unroll
        for (int nt2 = 0; nt2 < 8; nt2++) {
            asm volatile("mma.sync.aligned.m16n8k16.row.col.f32.f16.f16.f32 "
                         "{%0,%1,%2,%3}, {%4,%5,%6,%7}, {%8,%9}, {%0,%1,%2,%3};"
                         : "+f"(c[nt2 * 2][0]), "+f"(c[nt2 * 2][1]),
                           "+f"(c[nt2 * 2][2]), "+f"(c[nt2 * 2][3])
                         : "r"(a0), "r"(a1), "r"(a2), "r"(a3),
                           "r"(b[nt2][0]), "r"(b[nt2][1]));
            asm volatile("mma.sync.aligned.m16n8k16.row.col.f32.f16.f16.f32 "
                         "{%0,%1,%2,%3}, {%4,%5,%6,%7}, {%8,%9}, {%0,%1,%2,%3};"
                         : "+f"(c[nt2 * 2 + 1][0]), "+f"(c[nt2 * 2 + 1][1]),
                           "+f"(c[nt2 * 2 + 1][2]), "+f"(c[nt2 * 2 + 1][3])
                         : "r"(a0), "r"(a1), "r"(a2), "r"(a3),
                           "r"(b[nt2][2]), "r"(b[nt2][3]));
        }
    }

    int r0 = w * 16 + (lane >> 2);
    int r1 = r0 + 8;
    int cbase = (lane & 3) * 2;
    int gr0 = row0 + r0, gr1 = row0 + r1;

    #pragma unroll
    for (int nt = 0; nt < 16; nt++) {
        int col = nt * 8 + cbase;
        if (gr0 < NN)
            *(float2*)&g_feat1[gr0 * 128 + col] = make_float2(c[nt][0], c[nt][1]);
        if (gr1 < NN)
            *(float2*)&g_feat1[gr1 * 128 + col] = make_float2(c[nt][2], c[nt][3]);
    }

    #pragma unroll
    for (int h = 0; h < 8; h++) {
        float2 ala = *(const float2*)&al[h * 16 + cbase];
        float2 alb = *(const float2*)&al[h * 16 + 8 + cbase];
        float2 ara = *(const float2*)&ar[h * 16 + cbase];
        float2 arb = *(const float2*)&ar[h * 16 + 8 + cbase];
        const float* ca = c[2 * h];
        const float* cb = c[2 * h + 1];
        float el0 = ca[0] * ala.x + ca[1] * ala.y + cb[0] * alb.x + cb[1] * alb.y;
        float er0 = ca[0] * ara.x + ca[1] * ara.y + cb[0] * arb.x + cb[1] * arb.y;
        float el1 = ca[2] * ala.x + ca[3] * ala.y + cb[2] * alb.x + cb[3] * alb.y;
        float er1 = ca[2] * ara.x + ca[3] * ara.y + cb[2] * arb.x + cb[3] * arb.y;
        el0 += __shfl_xor_sync(0xffffffffu, el0, 1);
        el0 += __shfl_xor_sync(0xffffffffu, el0, 2);
        er0 += __shfl_xor_sync(0xffffffffu, er0, 1);
        er0 += __shfl_xor_sync(0xffffffffu, er0, 2);
        el1 += __shfl_xor_sync(0xffffffffu, el1, 1);
        el1 += __shfl_xor_sync(0xffffffffu, el1, 2);
        er1 += __shfl_xor_sync(0xffffffffu, er1, 1);
        er1 += __shfl_xor_sync(0xffffffffu, er1, 2);
        if ((lane & 3) == 0) {
            if (gr0 < NN) { g_el1[gr0 * 8 + h] = el0; g_er1[gr0 * 8 + h] = er0; }
            if (gr1 < NN) { g_el1[gr1 * 8 + h] = el1; g_er1[gr1 * 8 + h] = er1; }
        }
    }
}

// ---------------- layer1 fused softmax+aggregate (4-edge unroll, fp32) -------
__global__ void __launch_bounds__(256) k_node1(const float* __restrict__ b1) {
    int v = (blockIdx.x * blockDim.x + threadIdx.x) >> 5;
    if (v >= NN) return;
    int lane = threadIdx.x & 31;
    int h4 = lane >> 2;
    int beg = off_at(v), end = off_at(v + 1);
    float erh = g_er1[v * 8 + h4];

    float denom = 0.f;
    float4 acc = make_float4(0.f, 0.f, 0.f, 0.f);

    auto edge = [&](int s) {
        float e0 = g_el1[s * 8 + h4] + erh;
        float e = fmaxf(e0, 0.2f * e0);
        float w = __expf(e);
        float4 f = *(const float4*)&g_feat1[s * 128 + lane * 4];
        denom += w;
        acc.x += w * f.x; acc.y += w * f.y;
        acc.z += w * f.z; acc.w += w * f.w;
    };

    int p = beg;
    while ((p & 3) && p < end) { edge(g_csrc[p]); p++; }
    for (; p + 4 <= end; p += 4) {
        int4 ss = *(const int4*)&g_csrc[p];
        edge(ss.x); edge(ss.y); edge(ss.z); edge(ss.w);
    }
    for (; p < end; p++) edge(g_csrc[p]);

    float inv = 1.f / (denom + 1e-9f);
    float4 b = *(const float4*)&b1[lane * 4];
    float4 r;
    r.x = acc.x * inv + b.x; r.y = acc.y * inv + b.y;
    r.z = acc.z * inv + b.z; r.w = acc.w * inv + b.w;
    r.x = (r.x > 0.f) ? r.x : (__expf(r.x) - 1.f);
    r.y = (r.y > 0.f) ? r.y : (__expf(r.y) - 1.f);
    r.z = (r.z > 0.f) ? r.z : (__expf(r.z) - 1.f);
    r.w = (r.w > 0.f) ? r.w : (__expf(r.w) - 1.f);
    *(float4*)&g_h[v * 128 + lane * 4] = r;
}

// ---------------- GEMM2 + fused coef2 epilogue (fp32) ------------------------
__global__ void __launch_bounds__(240) k_gemm2(const float* __restrict__ W,
                                               const float* __restrict__ al,
                                               const float* __restrict__ ar) {
    __shared__ __align__(16) float Xs[48][129];
    __shared__ __align__(16) float Ws[128][40];
    __shared__ float pelA[240], perA[240], pelB[240], perB[240];
    int tid = threadIdx.x;
    int tc = tid % 10, rl = tid / 10;
    int row0 = blockIdx.x * 48;
    for (int i = tid; i < 48 * 128; i += 240) {
        int r = i >> 7, c = i & 127;
        int gr = row0 + r;
        Xs[r][c] = (gr < NN) ? g_h[gr * 128 + c] : 0.f;
    }
    for (int i = tid; i < 128 * 40; i += 240)
        Ws[i / 40][i % 40] = W[i];
    __syncthreads();

    float a0[4] = {0, 0, 0, 0}, a1[4] = {0, 0, 0, 0};
    #pragma unroll 4
    for (int k = 0; k < 128; k++) {
        float4 w = *(const float4*)&Ws[k][tc * 4];
        float xa = Xs[rl][k];
        float xb = Xs[rl + 24][k];
        a0[0] += xa * w.x; a0[1] += xa * w.y; a0[2] += xa * w.z; a0[3] += xa * w.w;
        a1[0] += xb * w.x; a1[1] += xb * w.y; a1[2] += xb * w.z; a1[3] += xb * w.w;
    }
    int ra = row0 + rl, rb = ra + 24;
    if (ra < NN)
        *(float4*)&g_feat2[ra * 40 + tc * 4] = make_float4(a0[0], a0[1], a0[2], a0[3]);
    if (rb < NN)
        *(float4*)&g_feat2[rb * 40 + tc * 4] = make_float4(a1[0], a1[1], a1[2], a1[3]);

    float4 av = *(const float4*)&al[tc * 4];
    float4 rv = *(const float4*)&ar[tc * 4];
    pelA[tid] = a0[0] * av.x + a0[1] * av.y + a0[2] * av.z + a0[3] * av.w;
    perA[tid] = a0[0] * rv.x + a0[1] * rv.y + a0[2] * rv.z + a0[3] * rv.w;
    pelB[tid] = a1[0] * av.x + a1[1] * av.y + a1[2] * av.z + a1[3] * av.w;
    perB[tid] = a1[0] * rv.x + a1[1] * rv.y + a1[2] * rv.z + a1[3] * rv.w;
    __syncthreads();
    if (tid < 48) {
        int r = (tid < 24) ? tid : (tid - 24);
        const float* pe = (tid < 24) ? pelA : pelB;
        const float* pr = (tid < 24) ? perA : perB;
        float el = 0.f, er = 0.f;
        #pragma unroll
        for (int j = 0; j < 10; j++) {
            el += pe[r * 10 + j];
            er += pr[r * 10 + j];
        }
        int gr = (tid < 24) ? (row0 + r) : (row0 + 24 + r);
        if (gr < NN) { g_el2[gr] = el; g_er2[gr] = er; }
    }
}

// ---------------- layer2 fused softmax+aggregate (4-edge unroll, fp32) -------
__global__ void __launch_bounds__(256) k_node2(const float* __restrict__ b2,
                                               float* __restrict__ out) {
    int v = (blockIdx.x * blockDim.x + threadIdx.x) >> 5;
    if (v >= NN) return;
    int lane = threadIdx.x & 31;
    int beg = off_at(v), end = off_at(v + 1);
    float erv = g_er2[v];
    bool act = lane < 20;

    float denom = 0.f;
    float2 acc = make_float2(0.f, 0.f);

    auto edge = [&](int s) {
        float e0 = g_el2[s] + erv;
        float e = fmaxf(e0, 0.2f * e0);
        float w = __expf(e);
        denom += w;
        if (act) {
            float2 f = *(const float2*)&g_feat2[s * 40 + lane * 2];
            acc.x += w * f.x;
            acc.y += w * f.y;
        }
    };

    int p = beg;
    while ((p & 3) && p < end) { edge(g_csrc[p]); p++; }
    for (; p + 4 <= end; p += 4) {
        int4 ss = *(const int4*)&g_csrc[p];
        edge(ss.x); edge(ss.y); edge(ss.z); edge(ss.w);
    }
    for (; p < end; p++) edge(g_csrc[p]);

    float inv = 1.f / (denom + 1e-9f);
    if (act) {
        float2 r;
        r.x = acc.x * inv + b2[lane * 2];
        r.y = acc.y * inv + b2[lane * 2 + 1];
        *(float2*)&out[v * 40 + lane * 2] = r;
    }
}

// ---------------- streams/events (created once, before main) ------------------
static cudaStream_t g_s2;
static cudaEvent_t g_evFork, g_evJoin;
static struct StreamInit {
    StreamInit() {
        cudaStreamCreate(&g_s2);
        cudaEventCreateWithFlags(&g_evFork, cudaEventDisableTiming);
        cudaEventCreateWithFlags(&g_evJoin, cudaEventDisableTiming);
    }
} g_stream_init;

// ---------------- launch ------------------------------------------------------
extern "C" void kernel_launch(void* const* d_in, const int* in_sizes, int n_in,
                              void* d_out, int out_size) {
    const float* features = (const float*)d_in[0];
    const int*   esrc     = (const int*)d_in[1];
    const int*   edst     = (const int*)d_in[2];
    const float* W1       = (const float*)d_in[3];
    const float* al1      = (const float*)d_in[4];
    const float* ar1      = (const float*)d_in[5];
    const float* b1       = (const float*)d_in[6];
    const float* W2       = (const float*)d_in[7];
    const float* al2      = (const float*)d_in[8];
    const float* ar2      = (const float*)d_in[9];
    const float* b2       = (const float*)d_in[10];
    float* out = (float*)d_out;

    // gemm1 issued FIRST on s2 (overlap restored, R13 ordering)
    cudaEventRecord(g_evFork, 0);
    cudaStreamWaitEvent(g_s2, g_evFork, 0);
    k_gemm1<<<(NN + 63) / 64, 128, 0, g_s2>>>(features, W1, al1, ar1);
    cudaEventRecord(g_evJoin, g_s2);

    // CSR chain on the main stream
    k_count<<<(EE / 2 + 255) / 256, 256>>>(edst);
    k_scanAB<<<NSB, SCAN_B>>>();
    k_scatter<<<(EE / 2 + 255) / 256, 256>>>(esrc, edst);

    // join, then the dependent tail
    cudaStreamWaitEvent(0, g_evJoin, 0);
    k_node1<<<(NN * 32 + 255) / 256, 256>>>(b1);
    k_gemm2<<<(NN + 47) / 48, 240>>>(W2, al2, ar2);
    k_node2<<<(NN * 32 + 255) / 256, 256>>>(b2, out);
}

// round 17
// speedup vs baseline: 1.6913x; 1.1664x over previous
#include <cuda_runtime.h>
#include <cuda_fp16.h>
#include <math.h>

#define NN 50000
#define EE 800000
#define HID 16
#define HEADS 8
#define F1 128   /* HEADS*HID */
#define CLS 40
#define SCAN_B 512
#define NSB ((NN + SCAN_B - 1) / SCAN_B)   /* 98 */

// ---------------- scratch ----------------------------------------------------
__device__ __align__(16) float g_feat1[NN * F1];
__device__ float g_el1[NN * HEADS];
__device__ float g_er1[NN * HEADS];
__device__ __align__(16) float g_h[NN * F1];
__device__ __align__(16) float g_feat2[NN * CLS];
__device__ float g_el2[NN];
__device__ float g_er2[NN];
__device__ int   g_deg[NN];        // zero-initialized; scanAB re-zeroes each run
__device__ int   g_off[NN];
__device__ int   g_bsum[NSB];
__device__ int   g_bofs[NSB];
__device__ __align__(16) int g_rank[EE];
__device__ __align__(16) int g_csrc[EE];
__device__ unsigned long long g_ctr = 0;   // monotonic (never reset)

__device__ __forceinline__ int off_at(int i) {
    return (i == NN) ? EE : (g_off[i] + g_bofs[i >> 9]);
}

// ---------------- CSR build --------------------------------------------------
__global__ void k_count(const int* __restrict__ dst) {
    int t = blockIdx.x * blockDim.x + threadIdx.x;
    if (t >= EE / 2) return;
    int2 d = ((const int2*)dst)[t];
    int2 r;
    r.x = atomicAdd(&g_deg[d.x], 1);
    r.y = atomicAdd(&g_deg[d.y], 1);
    ((int2*)g_rank)[t] = r;
}

__global__ void __launch_bounds__(SCAN_B) k_scanAB() {
    __shared__ int wsum[16];
    __shared__ int slast;
    int tid = threadIdx.x, lane = tid & 31, wid = tid >> 5;
    int i = blockIdx.x * SCAN_B + tid;
    int v = (i < NN) ? g_deg[i] : 0;
    if (i < NN) g_deg[i] = 0;       // self-clean for next graph replay
    int x = v;
    #pragma unroll
    for (int o = 1; o < 32; o <<= 1) {
        int y = __shfl_up_sync(0xffffffffu, x, o);
        if (lane >= o) x += y;
    }
    if (lane == 31) wsum[wid] = x;
    __syncthreads();
    if (wid == 0 && lane < 16) {
        int y = wsum[lane];
        #pragma unroll
        for (int o = 1; o < 16; o <<= 1) {
            int z = __shfl_up_sync(0x0000ffffu, y, o);
            if (lane >= o) y += z;
        }
        wsum[lane] = y;
    }
    __syncthreads();
    int wofs = wid ? wsum[wid - 1] : 0;
    if (i < NN) g_off[i] = wofs + x - v;
    if (tid == SCAN_B - 1) g_bsum[blockIdx.x] = wofs + x;

    __threadfence();
    if (tid == 0) {
        unsigned long long c = atomicAdd(&g_ctr, 1ULL);
        slast = ((c % (unsigned long long)NSB) == (unsigned long long)(NSB - 1));
    }
    __syncthreads();
    if (slast && tid < 32) {
        volatile int* bs = g_bsum;
        int carry = 0;
        #pragma unroll
        for (int c = 0; c < (NSB + 31) / 32; c++) {
            int j = c * 32 + tid;
            int vv = (j < NSB) ? bs[j] : 0;
            int xx = vv;
            #pragma unroll
            for (int o = 1; o < 32; o <<= 1) {
                int y = __shfl_up_sync(0xffffffffu, xx, o);
                if (tid >= o) xx += y;
            }
            if (j < NSB) g_bofs[j] = carry + xx - vv;
            carry += __shfl_sync(0xffffffffu, xx, 31);
        }
    }
}

__global__ void k_scatter(const int* __restrict__ src, const int* __restrict__ dst) {
    int t = blockIdx.x * blockDim.x + threadIdx.x;
    if (t >= EE / 2) return;
    int2 d = ((const int2*)dst)[t];
    int2 s = ((const int2*)src)[t];
    int2 r = ((const int2*)g_rank)[t];
    g_csrc[g_off[d.x] + g_bofs[d.x >> 9] + r.x] = s.x;
    g_csrc[g_off[d.y] + g_bofs[d.y >> 9] + r.y] = s.y;
}

// ---------------- GEMM1 via tensor cores (mma.sync m16n8k16) -----------------
__global__ void __launch_bounds__(128) k_gemm1(const float* __restrict__ X,
                                               const float* __restrict__ W,
                                               const float* __restrict__ al,
                                               const float* __restrict__ ar) {
    __shared__ __half Xs[64][136];    // row stride 272B
    __shared__ __half Ws[128][136];
    int tid = threadIdx.x;
    int lane = tid & 31, w = tid >> 5;
    int row0 = blockIdx.x * 64;

    for (int i = tid; i < 2048; i += 128) {
        int r = i >> 5, c4 = (i & 31) * 4;
        int gr = row0 + r;
        float4 v = (gr < NN) ? *(const float4*)&X[gr * 128 + c4]
                             : make_float4(0.f, 0.f, 0.f, 0.f);
        *(__half2*)&Xs[r][c4]     = __floats2half2_rn(v.x, v.y);
        *(__half2*)&Xs[r][c4 + 2] = __floats2half2_rn(v.z, v.w);
    }
    for (int i = tid; i < 4096; i += 128) {
        int r = i >> 5, c4 = (i & 31) * 4;
        float4 v = *(const float4*)&W[r * 128 + c4];
        *(__half2*)&Ws[r][c4]     = __floats2half2_rn(v.x, v.y);
        *(__half2*)&Ws[r][c4 + 2] = __floats2half2_rn(v.z, v.w);
    }
    __syncthreads();

    float c[16][4];
    #pragma unroll
    for (int n = 0; n < 16; n++)
        #pragma unroll
        for (int j = 0; j < 4; j++) c[n][j] = 0.f;

    int mrow = (lane & 7) + ((lane >> 3) & 1) * 8;
    int mcol = (lane >> 4) * 8;
    unsigned xa = (unsigned)__cvta_generic_to_shared(&Xs[w * 16 + mrow][mcol]);
    unsigned wa = (unsigned)__cvta_generic_to_shared(&Ws[mrow][mcol]);

    #pragma unroll
    for (int ks = 0; ks < 8; ks++) {
        unsigned a0, a1, a2, a3;
        asm volatile("ldmatrix.sync.aligned.m8n8.x4.shared.b16 {%0,%1,%2,%3}, [%4];"
                     : "=r"(a0), "=r"(a1), "=r"(a2), "=r"(a3)
                     : "r"(xa + ks * 32));
        unsigned b[8][4];
        #pragma unroll
        for (int nt2 = 0; nt2 < 8; nt2++) {
            asm volatile("ldmatrix.sync.aligned.m8n8.x4.trans.shared.b16 {%0,%1,%2,%3}, [%4];"
                         : "=r"(b[nt2][0]), "=r"(b[nt2][1]),
                           "=r"(b[nt2][2]), "=r"(b[nt2][3])
                         : "r"(wa + ks * (16 * 272) + nt2 * 32));
        }
        #pragma unroll
        for (int nt2 = 0; nt2 < 8; nt2++) {
            asm volatile("mma.sync.aligned.m16n8k16.row.col.f32.f16.f16.f32 "
                         "{%0,%1,%2,%3}, {%4,%5,%6,%7}, {%8,%9}, {%0,%1,%2,%3};"
                         : "+f"(c[nt2 * 2][0]), "+f"(c[nt2 * 2][1]),
                           "+f"(c[nt2 * 2][2]), "+f"(c[nt2 * 2][3])
                         : "r"(a0), "r"(a1), "r"(a2), "r"(a3),
                           "r"(b[nt2][0]), "r"(b[nt2][1]));
            asm volatile("mma.sync.aligned.m16n8k16.row.col.f32.f16.f16.f32 "
                         "{%0,%1,%2,%3}, {%4,%5,%6,%7}, {%8,%9}, {%0,%1,%2,%3};"
                         : "+f"(c[nt2 * 2 + 1][0]), "+f"(c[nt2 * 2 + 1][1]),
                           "+f"(c[nt2 * 2 + 1][2]), "+f"(c[nt2 * 2 + 1][3])
                         : "r"(a0), "r"(a1), "r"(a2), "r"(a3),
                           "r"(b[nt2][2]), "r"(b[nt2][3]));
        }
    }

    int r0 = w * 16 + (lane >> 2);
    int r1 = r0 + 8;
    int cbase = (lane & 3) * 2;
    int gr0 = row0 + r0, gr1 = row0 + r1;

    #pragma unroll
    for (int nt = 0; nt < 16; nt++) {
        int col = nt * 8 + cbase;
        if (gr0 < NN)
            *(float2*)&g_feat1[gr0 * 128 + col] = make_float2(c[nt][0], c[nt][1]);
        if (gr1 < NN)
            *(float2*)&g_feat1[gr1 * 128 + col] = make_float2(c[nt][2], c[nt][3]);
    }

    #pragma unroll
    for (int h = 0; h < 8; h++) {
        float2 ala = *(const float2*)&al[h * 16 + cbase];
        float2 alb = *(const float2*)&al[h * 16 + 8 + cbase];
        float2 ara = *(const float2*)&ar[h * 16 + cbase];
        float2 arb = *(const float2*)&ar[h * 16 + 8 + cbase];
        const float* ca = c[2 * h];
        const float* cb = c[2 * h + 1];
        float el0 = ca[0] * ala.x + ca[1] * ala.y + cb[0] * alb.x + cb[1] * alb.y;
        float er0 = ca[0] * ara.x + ca[1] * ara.y + cb[0] * arb.x + cb[1] * arb.y;
        float el1 = ca[2] * ala.x + ca[3] * ala.y + cb[2] * alb.x + cb[3] * alb.y;
        float er1 = ca[2] * ara.x + ca[3] * ara.y + cb[2] * arb.x + cb[3] * arb.y;
        el0 += __shfl_xor_sync(0xffffffffu, el0, 1);
        el0 += __shfl_xor_sync(0xffffffffu, el0, 2);
        er0 += __shfl_xor_sync(0xffffffffu, er0, 1);
        er0 += __shfl_xor_sync(0xffffffffu, er0, 2);
        el1 += __shfl_xor_sync(0xffffffffu, el1, 1);
        el1 += __shfl_xor_sync(0xffffffffu, el1, 2);
        er1 += __shfl_xor_sync(0xffffffffu, er1, 1);
        er1 += __shfl_xor_sync(0xffffffffu, er1, 2);
        if ((lane & 3) == 0) {
            if (gr0 < NN) { g_el1[gr0 * 8 + h] = el0; g_er1[gr0 * 8 + h] = er0; }
            if (gr1 < NN) { g_el1[gr1 * 8 + h] = el1; g_er1[gr1 * 8 + h] = er1; }
        }
    }
}

// ---------------- layer1 fused softmax+aggregate (8-edge unroll, fp32) -------
__global__ void __launch_bounds__(256) k_node1(const float* __restrict__ b1) {
    int v = (blockIdx.x * blockDim.x + threadIdx.x) >> 5;
    if (v >= NN) return;
    int lane = threadIdx.x & 31;
    int h4 = lane >> 2;
    int beg = off_at(v), end = off_at(v + 1);
    float erh = g_er1[v * 8 + h4];

    float denom = 0.f;
    float4 acc = make_float4(0.f, 0.f, 0.f, 0.f);

    auto edge = [&](int s) {
        float e0 = g_el1[s * 8 + h4] + erh;
        float e = fmaxf(e0, 0.2f * e0);
        float w = __expf(e);
        float4 f = *(const float4*)&g_feat1[s * 128 + lane * 4];
        denom += w;
        acc.x += w * f.x; acc.y += w * f.y;
        acc.z += w * f.z; acc.w += w * f.w;
    };

    int p = beg;
    while ((p & 3) && p < end) { edge(g_csrc[p]); p++; }
    for (; p + 8 <= end; p += 8) {
        int4 sa = *(const int4*)&g_csrc[p];
        int4 sb = *(const int4*)&g_csrc[p + 4];
        edge(sa.x); edge(sa.y); edge(sa.z); edge(sa.w);
        edge(sb.x); edge(sb.y); edge(sb.z); edge(sb.w);
    }
    for (; p + 4 <= end; p += 4) {
        int4 ss = *(const int4*)&g_csrc[p];
        edge(ss.x); edge(ss.y); edge(ss.z); edge(ss.w);
    }
    for (; p < end; p++) edge(g_csrc[p]);

    float inv = 1.f / (denom + 1e-9f);
    float4 b = *(const float4*)&b1[lane * 4];
    float4 r;
    r.x = acc.x * inv + b.x; r.y = acc.y * inv + b.y;
    r.z = acc.z * inv + b.z; r.w = acc.w * inv + b.w;
    r.x = (r.x > 0.f) ? r.x : (__expf(r.x) - 1.f);
    r.y = (r.y > 0.f) ? r.y : (__expf(r.y) - 1.f);
    r.z = (r.z > 0.f) ? r.z : (__expf(r.z) - 1.f);
    r.w = (r.w > 0.f) ? r.w : (__expf(r.w) - 1.f);
    *(float4*)&g_h[v * 128 + lane * 4] = r;
}

// ---------------- GEMM2 via tensor cores + fused coef2 epilogue --------------
// 64 rows x 40 cols (padded to 48 in smem); 4 warps, K=128 resident.
__global__ void __launch_bounds__(128) k_gemm2(const float* __restrict__ W,
                                               const float* __restrict__ al,
                                               const float* __restrict__ ar) {
    __shared__ __half Hs[64][136];    // row stride 272B
    __shared__ __half Ws2[128][56];   // row stride 112B (16B mult, cf-free)
    int tid = threadIdx.x;
    int lane = tid & 31, w = tid >> 5;
    int row0 = blockIdx.x * 64;

    // load h tile -> fp16
    for (int i = tid; i < 2048; i += 128) {
        int r = i >> 5, c4 = (i & 31) * 4;
        int gr = row0 + r;
        float4 v = (gr < NN) ? *(const float4*)&g_h[gr * 128 + c4]
                             : make_float4(0.f, 0.f, 0.f, 0.f);
        *(__half2*)&Hs[r][c4]     = __floats2half2_rn(v.x, v.y);
        *(__half2*)&Hs[r][c4 + 2] = __floats2half2_rn(v.z, v.w);
    }
    // zero pad cols 40-55, then load W2 (128x40) -> fp16
    for (int i = tid; i < 128 * 8; i += 128) {
        int r = i >> 3, c2 = (i & 7) * 2;
        *(__half2*)&Ws2[r][40 + c2] = __floats2half2_rn(0.f, 0.f);
    }
    for (int i = tid; i < 128 * 20; i += 128) {
        int r = i / 20, c2 = (i % 20) * 2;
        float2 v = *(const float2*)&W[r * 40 + c2];
        *(__half2*)&Ws2[r][c2] = __floats2half2_rn(v.x, v.y);
    }
    __syncthreads();

    float c[6][4];
    #pragma unroll
    for (int n = 0; n < 6; n++)
        #pragma unroll
        for (int j = 0; j < 4; j++) c[n][j] = 0.f;

    int mrow = (lane & 7) + ((lane >> 3) & 1) * 8;
    int mcol = (lane >> 4) * 8;
    unsigned ha = (unsigned)__cvta_generic_to_shared(&Hs[w * 16 + mrow][mcol]);
    unsigned wa = (unsigned)__cvta_generic_to_shared(&Ws2[mrow][mcol]);

    #pragma unroll
    for (int ks = 0; ks < 8; ks++) {
        unsigned a0, a1, a2, a3;
        asm volatile("ldmatrix.sync.aligned.m8n8.x4.shared.b16 {%0,%1,%2,%3}, [%4];"
                     : "=r"(a0), "=r"(a1), "=r"(a2), "=r"(a3)
                     : "r"(ha + ks * 32));
        unsigned b[3][4];
        #pragma unroll
        for (int nt2 = 0; nt2 < 3; nt2++) {
            asm volatile("ldmatrix.sync.aligned.m8n8.x4.trans.shared.b16 {%0,%1,%2,%3}, [%4];"
                         : "=r"(b[nt2][0]), "=r"(b[nt2][1]),
                           "=r"(b[nt2][2]), "=r"(b[nt2][3])
                         : "r"(wa + ks * (16 * 112) + nt2 * 32));
        }
        #pragma unroll
        for (int nt2 = 0; nt2 < 3; nt2++) {
            asm volatile("mma.sync.aligned.m16n8k16.row.col.f32.f16.f16.f32 "
                         "{%0,%1,%2,%3}, {%4,%5,%6,%7}, {%8,%9}, {%0,%1,%2,%3};"
                         : "+f"(c[nt2 * 2][0]), "+f"(c[nt2 * 2][1]),
                           "+f"(c[nt2 * 2][2]), "+f"(c[nt2 * 2][3])
                         : "r"(a0), "r"(a1), "r"(a2), "r"(a3),
                           "r"(b[nt2][0]), "r"(b[nt2][1]));
            asm volatile("mma.sync.aligned.m16n8k16.row.col.f32.f16.f16.f32 "
                         "{%0,%1,%2,%3}, {%4,%5,%6,%7}, {%8,%9}, {%0,%1,%2,%3};"
                         : "+f"(c[nt2 * 2 + 1][0]), "+f"(c[nt2 * 2 + 1][1]),
                           "+f"(c[nt2 * 2 + 1][2]), "+f"(c[nt2 * 2 + 1][3])
                         : "r"(a0), "r"(a1), "r"(a2), "r"(a3),
                           "r"(b[nt2][2]), "r"(b[nt2][3]));
        }
    }

    int r0 = w * 16 + (lane >> 2);
    int r1 = r0 + 8;
    int cbase = (lane & 3) * 2;
    int gr0 = row0 + r0, gr1 = row0 + r1;

    // store feat2 (cols 0..39 only: n-tiles 0..4)
    #pragma unroll
    for (int nt = 0; nt < 5; nt++) {
        int col = nt * 8 + cbase;
        if (gr0 < NN)
            *(float2*)&g_feat2[gr0 * 40 + col] = make_float2(c[nt][0], c[nt][1]);
        if (gr1 < NN)
            *(float2*)&g_feat2[gr1 * 40 + col] = make_float2(c[nt][2], c[nt][3]);
    }

    // fused coef2: lane's partial dot over its 10 owned cols; quad-reduce
    float el0 = 0.f, er0 = 0.f, el1 = 0.f, er1 = 0.f;
    #pragma unroll
    for (int nt = 0; nt < 5; nt++) {
        int col = nt * 8 + cbase;
        float2 av = *(const float2*)&al[col];
        float2 rv = *(const float2*)&ar[col];
        el0 += c[nt][0] * av.x + c[nt][1] * av.y;
        er0 += c[nt][0] * rv.x + c[nt][1] * rv.y;
        el1 += c[nt][2] * av.x + c[nt][3] * av.y;
        er1 += c[nt][2] * rv.x + c[nt][3] * rv.y;
    }
    el0 += __shfl_xor_sync(0xffffffffu, el0, 1);
    el0 += __shfl_xor_sync(0xffffffffu, el0, 2);
    er0 += __shfl_xor_sync(0xffffffffu, er0, 1);
    er0 += __shfl_xor_sync(0xffffffffu, er0, 2);
    el1 += __shfl_xor_sync(0xffffffffu, el1, 1);
    el1 += __shfl_xor_sync(0xffffffffu, el1, 2);
    er1 += __shfl_xor_sync(0xffffffffu, er1, 1);
    er1 += __shfl_xor_sync(0xffffffffu, er1, 2);
    if ((lane & 3) == 0) {
        if (gr0 < NN) { g_el2[gr0] = el0; g_er2[gr0] = er0; }
        if (gr1 < NN) { g_el2[gr1] = el1; g_er2[gr1] = er1; }
    }
}

// ---------------- layer2 fused softmax+aggregate (4-edge unroll, fp32) -------
__global__ void __launch_bounds__(256) k_node2(const float* __restrict__ b2,
                                               float* __restrict__ out) {
    int v = (blockIdx.x * blockDim.x + threadIdx.x) >> 5;
    if (v >= NN) return;
    int lane = threadIdx.x & 31;
    int beg = off_at(v), end = off_at(v + 1);
    float erv = g_er2[v];
    bool act = lane < 20;

    float denom = 0.f;
    float2 acc = make_float2(0.f, 0.f);

    auto edge = [&](int s) {
        float e0 = g_el2[s] + erv;
        float e = fmaxf(e0, 0.2f * e0);
        float w = __expf(e);
        denom += w;
        if (act) {
            float2 f = *(const float2*)&g_feat2[s * 40 + lane * 2];
            acc.x += w * f.x;
            acc.y += w * f.y;
        }
    };

    int p = beg;
    while ((p & 3) && p < end) { edge(g_csrc[p]); p++; }
    for (; p + 4 <= end; p += 4) {
        int4 ss = *(const int4*)&g_csrc[p];
        edge(ss.x); edge(ss.y); edge(ss.z); edge(ss.w);
    }
    for (; p < end; p++) edge(g_csrc[p]);

    float inv = 1.f / (denom + 1e-9f);
    if (act) {
        float2 r;
        r.x = acc.x * inv + b2[lane * 2];
        r.y = acc.y * inv + b2[lane * 2 + 1];
        *(float2*)&out[v * 40 + lane * 2] = r;
    }
}

// ---------------- streams/events (created once, before main) ------------------
static cudaStream_t g_s2;
static cudaEvent_t g_evFork, g_evJoin;
static struct StreamInit {
    StreamInit() {
        cudaStreamCreate(&g_s2);
        cudaEventCreateWithFlags(&g_evFork, cudaEventDisableTiming);
        cudaEventCreateWithFlags(&g_evJoin, cudaEventDisableTiming);
    }
} g_stream_init;

// ---------------- launch ------------------------------------------------------
extern "C" void kernel_launch(void* const* d_in, const int* in_sizes, int n_in,
                              void* d_out, int out_size) {
    const float* features = (const float*)d_in[0];
    const int*   esrc     = (const int*)d_in[1];
    const int*   edst     = (const int*)d_in[2];
    const float* W1       = (const float*)d_in[3];
    const float* al1      = (const float*)d_in[4];
    const float* ar1      = (const float*)d_in[5];
    const float* b1       = (const float*)d_in[6];
    const float* W2       = (const float*)d_in[7];
    const float* al2      = (const float*)d_in[8];
    const float* ar2      = (const float*)d_in[9];
    const float* b2       = (const float*)d_in[10];
    float* out = (float*)d_out;

    // gemm1 issued FIRST on s2 (overlap with CSR chain)
    cudaEventRecord(g_evFork, 0);
    cudaStreamWaitEvent(g_s2, g_evFork, 0);
    k_gemm1<<<(NN + 63) / 64, 128, 0, g_s2>>>(features, W1, al1, ar1);
    cudaEventRecord(g_evJoin, g_s2);

    // CSR chain on the main stream
    k_count<<<(EE / 2 + 255) / 256, 256>>>(edst);
    k_scanAB<<<NSB, SCAN_B>>>();
    k_scatter<<<(EE / 2 + 255) / 256, 256>>>(esrc, edst);

    // join, then the dependent tail
    cudaStreamWaitEvent(0, g_evJoin, 0);
    k_node1<<<(NN * 32 + 255) / 256, 256>>>(b1);
    k_gemm2<<<(NN + 63) / 64, 128>>>(W2, al2, ar2);
    k_node2<<<(NN * 32 + 255) / 256, 256>>>(b2, out);
}